// round 8
// baseline (speedup 1.0000x reference)
#include <cuda_runtime.h>

// ---------------------------------------------------------------------------
// ClusterInversionLoss — single persistent kernel + dynamic work stealing.
// (Resubmission of R7 after broker-side container failure; kernel audited for
//  hang vectors: uniform break conditions, guaranteed 6-CTA/SM residency for
//  the spin barrier, all counters reset for graph replay.)
//   Phase 1 (pack): s = E[class|softmax]; pack (y:3|s:17|w:12) into uint32
//     table with an L2::evict_last access policy (R5-verified: table stays
//     L2-resident, DRAM traffic == compulsory).
//   Both phases claim 1024-element chunks from a global counter, with the
//     NEXT chunk claimed while the current one runs (double-buffered claim)
//     -> all blocks reach the grid barrier / kernel end together.
//   grid barrier (888 blocks co-resident under launch_bounds(256,6))
//   Phase 2 (pairs): int4 index loads (evict_first), 4B policy-hinted table
//     gathers, branchless pair math, block partials + last-block reduction.
// ---------------------------------------------------------------------------

#define TPB    256
#define BPSM   6
#define GRID   (148 * BPSM)   /* 888 blocks, all co-resident */
#define N_MAX  4000000
#define CHUNK1 256            /* t-units (4 rows each) per claim = 1024 rows */
#define CHUNK2 256            /* int4-pair units per claim = 1024 pairs */

#define S_BITS  17
#define W_BITS  12
#define S_SCALE (131071.0f / 4.0f)
#define S_INV   (4.0f / 131071.0f)
#define W_SCALE 4095.0f
#define W_INV   (1.0f / 4095.0f)

__device__ unsigned int g_tab[N_MAX];
__device__ float2       g_part[GRID];
__device__ unsigned int g_bar   = 0;   // phase barrier arrive counter
__device__ unsigned int g_count = 0;   // final-reduction ticket
__device__ unsigned int g_w1    = 0;   // phase-1 work counter
__device__ unsigned int g_w2    = 0;   // phase-2 work counter

__device__ __forceinline__ unsigned long long evict_last_policy() {
    unsigned long long p;
    asm("createpolicy.fractional.L2::evict_last.b64 %0, 1.0;" : "=l"(p));
    return p;
}

__device__ __forceinline__ float score5(float v0, float v1, float v2,
                                        float v3, float v4) {
    float m  = fmaxf(fmaxf(fmaxf(v0, v1), fmaxf(v2, v3)), v4);
    float e0 = __expf(v0 - m);
    float e1 = __expf(v1 - m);
    float e2 = __expf(v2 - m);
    float e3 = __expf(v3 - m);
    float e4 = __expf(v4 - m);
    float se = e0 + e1 + e2 + e3 + e4;
    float sw = e1 + 2.0f * e2 + 3.0f * e3 + 4.0f * e4;
    return sw / se;
}

__device__ __forceinline__ unsigned int pack_row(float s, int y, float w) {
    unsigned int su = (unsigned int)__float2int_rn(s * S_SCALE);
    unsigned int wu = (unsigned int)__float2int_rn(w * W_SCALE);
    return ((unsigned int)y << (S_BITS + W_BITS)) | (su << W_BITS) | wu;
}

__device__ __forceinline__ void st_tab4(unsigned int* p, uint4 v,
                                        unsigned long long pol) {
    asm volatile("st.global.L2::cache_hint.v4.u32 [%0], {%1,%2,%3,%4}, %5;"
                 :: "l"(p), "r"(v.x), "r"(v.y), "r"(v.z), "r"(v.w), "l"(pol)
                 : "memory");
}

__device__ __forceinline__ unsigned int ld_tab(const unsigned int* p,
                                               unsigned long long pol) {
    unsigned int v;
    asm("ld.global.nc.L2::cache_hint.u32 %0, [%1], %2;"
        : "=r"(v) : "l"(p), "l"(pol));
    return v;
}

__device__ __forceinline__ void do_pair(int ia, int ib,
                                        unsigned long long pol,
                                        float& lsum, float& wsum) {
    unsigned int A = ld_tab(g_tab + ia, pol);
    unsigned int B = ld_tab(g_tab + ib, pol);
    int yA = (int)(A >> (S_BITS + W_BITS));
    int yB = (int)(B >> (S_BITS + W_BITS));
    int dy = yA - yB;
    float sA = (float)((A >> W_BITS) & 0x1FFFFu) * S_INV;
    float sB = (float)((B >> W_BITS) & 0x1FFFFu) * S_INV;
    float wA = (float)(A & 0xFFFu) * W_INV;
    float wB = (float)(B & 0xFFFu) * W_INV;
    float fdy = (float)dy;
    float sgn = (dy > 0) ? 1.0f : -1.0f;        // value irrelevant when dy==0
    float x   = -sgn * (sA - sB);               // MARGIN = 0
    float sp  = fmaxf(x, 0.0f) + log1pf(__expf(-fabsf(x)));
    float w   = (dy != 0) ? 0.5f * (wA + wB) : 0.0f;  // active mask folded in
    lsum = fmaf(sp * fabsf(fdy), w, lsum);
    wsum += w;
}

__global__ void __launch_bounds__(TPB, BPSM)
k_fused(const float* __restrict__ inputs,
        const int*   __restrict__ targets,
        const float* __restrict__ weight,
        const int*   __restrict__ pair_i,
        const int*   __restrict__ pair_j,
        int n, int np, float* __restrict__ out) {
    int gtid = blockIdx.x * blockDim.x + threadIdx.x;
    unsigned long long pol = evict_last_policy();
    __shared__ int s_base[2];

    // ================= Phase 1: pack table (work-stealing) =================
    int n4 = n >> 2;
    const float4* in4 = (const float4*)inputs;
    if (threadIdx.x == 0)
        s_base[0] = (int)atomicAdd(&g_w1, (unsigned int)CHUNK1);
    __syncthreads();
    int buf = 0;
    while (true) {
        int base = s_base[buf];
        if (threadIdx.x == 0)
            s_base[buf ^ 1] = (int)atomicAdd(&g_w1, (unsigned int)CHUNK1);
        if (base >= n4) break;                 // uniform: all exit together
        int end = min(base + CHUNK1, n4);
        for (int t = base + (int)threadIdx.x; t < end; t += TPB) {
            float4 a = __ldcs(in4 + 5 * (size_t)t + 0);
            float4 b = __ldcs(in4 + 5 * (size_t)t + 1);
            float4 c = __ldcs(in4 + 5 * (size_t)t + 2);
            float4 d = __ldcs(in4 + 5 * (size_t)t + 3);
            float4 e = __ldcs(in4 + 5 * (size_t)t + 4);
            float s0 = score5(a.x, a.y, a.z, a.w, b.x);
            float s1 = score5(b.y, b.z, b.w, c.x, c.y);
            float s2 = score5(c.z, c.w, d.x, d.y, d.z);
            float s3 = score5(d.w, e.x, e.y, e.z, e.w);
            int4   y = __ldcs((const int4*)targets + t);
            float4 w = __ldcs((const float4*)weight + t);
            uint4 o;
            o.x = pack_row(s0, y.x, w.x);
            o.y = pack_row(s1, y.y, w.y);
            o.z = pack_row(s2, y.z, w.z);
            o.w = pack_row(s3, y.w, w.w);
            st_tab4(g_tab + 4 * (size_t)t, o, pol);
        }
        buf ^= 1;
        __syncthreads();
    }
    int rem = n & 3;
    if (gtid < rem) {
        int i = (n4 << 2) + gtid;
        const float* r = inputs + (size_t)i * 5;
        float s = score5(__ldcs(r + 0), __ldcs(r + 1), __ldcs(r + 2),
                         __ldcs(r + 3), __ldcs(r + 4));
        g_tab[i] = pack_row(s, __ldcs(targets + i), __ldcs(weight + i));
    }

    // ================= Grid barrier (all blocks resident) =================
    __threadfence();
    __syncthreads();
    if (threadIdx.x == 0) {
        atomicAdd(&g_bar, 1u);
        volatile unsigned int* bar = &g_bar;
        while (*bar < gridDim.x) { __nanosleep(64); }
    }
    __syncthreads();
    __threadfence();

    // ================= Phase 2: pairs (work-stealing) =================
    float lsum = 0.0f, wsum = 0.0f;
    int np4 = np >> 2;
    const int4* pi4 = (const int4*)pair_i;
    const int4* pj4 = (const int4*)pair_j;
    if (threadIdx.x == 0)
        s_base[0] = (int)atomicAdd(&g_w2, (unsigned int)CHUNK2);
    __syncthreads();
    buf = 0;
    while (true) {
        int base = s_base[buf];
        if (threadIdx.x == 0)
            s_base[buf ^ 1] = (int)atomicAdd(&g_w2, (unsigned int)CHUNK2);
        if (base >= np4) break;                // uniform
        int end = min(base + CHUNK2, np4);
        for (int p = base + (int)threadIdx.x; p < end; p += TPB) {
            int4 ia = __ldcs(pi4 + p);
            int4 ib = __ldcs(pj4 + p);
            do_pair(ia.x, ib.x, pol, lsum, wsum);
            do_pair(ia.y, ib.y, pol, lsum, wsum);
            do_pair(ia.z, ib.z, pol, lsum, wsum);
            do_pair(ia.w, ib.w, pol, lsum, wsum);
        }
        buf ^= 1;
        __syncthreads();
    }
    if (gtid < (np & 3)) {
        int idx = (np4 << 2) + gtid;
        do_pair(__ldg(pair_i + idx), __ldg(pair_j + idx), pol, lsum, wsum);
    }

    // ---- block reduction ----
    #pragma unroll
    for (int o = 16; o > 0; o >>= 1) {
        lsum += __shfl_down_sync(0xffffffffu, lsum, o);
        wsum += __shfl_down_sync(0xffffffffu, wsum, o);
    }
    __shared__ float s_l[TPB / 32];
    __shared__ float s_w[TPB / 32];
    int lane = threadIdx.x & 31;
    int wid  = threadIdx.x >> 5;
    if (lane == 0) { s_l[wid] = lsum; s_w[wid] = wsum; }
    __syncthreads();
    if (wid == 0) {
        int nw = blockDim.x >> 5;
        lsum = (lane < nw) ? s_l[lane] : 0.0f;
        wsum = (lane < nw) ? s_w[lane] : 0.0f;
        #pragma unroll
        for (int o = 4; o > 0; o >>= 1) {
            lsum += __shfl_down_sync(0xffffffffu, lsum, o);
            wsum += __shfl_down_sync(0xffffffffu, wsum, o);
        }
        if (lane == 0) g_part[blockIdx.x] = make_float2(lsum, wsum);
    }

    // ---- last block: fold partials, write out, reset counters ----
    __threadfence();
    __shared__ bool is_last;
    if (threadIdx.x == 0) {
        unsigned int old = atomicAdd(&g_count, 1u);
        is_last = (old == gridDim.x - 1);
    }
    __syncthreads();
    if (is_last) {
        double l = 0.0, w = 0.0;
        for (int i = threadIdx.x; i < GRID; i += blockDim.x) {
            float2 pr = g_part[i];
            l += (double)pr.x;
            w += (double)pr.y;
        }
        #pragma unroll
        for (int o = 16; o > 0; o >>= 1) {
            l += __shfl_down_sync(0xffffffffu, l, o);
            w += __shfl_down_sync(0xffffffffu, w, o);
        }
        __shared__ double d_l[TPB / 32];
        __shared__ double d_w[TPB / 32];
        if (lane == 0) { d_l[wid] = l; d_w[wid] = w; }
        __syncthreads();
        if (wid == 0) {
            int nw = blockDim.x >> 5;
            l = (lane < nw) ? d_l[lane] : 0.0;
            w = (lane < nw) ? d_w[lane] : 0.0;
            #pragma unroll
            for (int o = 4; o > 0; o >>= 1) {
                l += __shfl_down_sync(0xffffffffu, l, o);
                w += __shfl_down_sync(0xffffffffu, w, o);
            }
            if (lane == 0) {
                out[0]  = (float)(l / (w + 1e-8));
                g_count = 0;     // reset everything for next graph replay
                g_bar   = 0;
                g_w1    = 0;
                g_w2    = 0;
            }
        }
    }
}

extern "C" void kernel_launch(void* const* d_in, const int* in_sizes, int n_in,
                              void* d_out, int out_size) {
    // metadata order: inputs, targets, cluster_ids, sample_weight, pair_i, pair_j
    const float* inputs  = (const float*)d_in[0];
    const int*   targets = (const int*)  d_in[1];
    const float* weight  = (const float*)d_in[3];
    const int*   pair_i  = (const int*)  d_in[4];
    const int*   pair_j  = (const int*)  d_in[5];

    int n  = in_sizes[1];
    int np = in_sizes[4];

    k_fused<<<GRID, TPB>>>(inputs, targets, weight, pair_i, pair_j,
                           n, np, (float*)d_out);
}

// round 9
// speedup vs baseline: 1.1170x; 1.1170x over previous
#include <cuda_runtime.h>

// ---------------------------------------------------------------------------
// ClusterInversionLoss — single persistent kernel (R5 structure restored:
// static grid-stride, occ 4). R9 change: phase-2 software pipeline —
// 8 table gathers per int4-group are front-batched into registers before any
// compute, and the NEXT iteration's pair indices are loaded while the current
// group's gathers are in flight (per-thread MLP ~2 -> ~10).
//   Phase 1 (pack): s = E[class|softmax]; pack (y:3|s:17|w:12) into uint32
//     table with an L2::evict_last access policy (R5-verified resident).
//   grid barrier (592 blocks co-resident under launch_bounds(256,4))
//   Phase 2 (pairs): pipelined gathers, block partials + last-block reduce.
// ---------------------------------------------------------------------------

#define TPB    256
#define BPSM   4
#define GRID   (148 * BPSM)   /* 592 blocks, all co-resident */
#define N_MAX  4000000

#define S_BITS  17
#define W_BITS  12
#define S_SCALE (131071.0f / 4.0f)
#define S_INV   (4.0f / 131071.0f)
#define W_SCALE 4095.0f
#define W_INV   (1.0f / 4095.0f)

__device__ unsigned int g_tab[N_MAX];
__device__ float2       g_part[GRID];
__device__ unsigned int g_bar   = 0;   // phase barrier arrive counter
__device__ unsigned int g_count = 0;   // final-reduction ticket

__device__ __forceinline__ unsigned long long evict_last_policy() {
    unsigned long long p;
    asm("createpolicy.fractional.L2::evict_last.b64 %0, 1.0;" : "=l"(p));
    return p;
}

__device__ __forceinline__ float score5(float v0, float v1, float v2,
                                        float v3, float v4) {
    float m  = fmaxf(fmaxf(fmaxf(v0, v1), fmaxf(v2, v3)), v4);
    float e0 = __expf(v0 - m);
    float e1 = __expf(v1 - m);
    float e2 = __expf(v2 - m);
    float e3 = __expf(v3 - m);
    float e4 = __expf(v4 - m);
    float se = e0 + e1 + e2 + e3 + e4;
    float sw = e1 + 2.0f * e2 + 3.0f * e3 + 4.0f * e4;
    return sw / se;
}

__device__ __forceinline__ unsigned int pack_row(float s, int y, float w) {
    unsigned int su = (unsigned int)__float2int_rn(s * S_SCALE);
    unsigned int wu = (unsigned int)__float2int_rn(w * W_SCALE);
    return ((unsigned int)y << (S_BITS + W_BITS)) | (su << W_BITS) | wu;
}

__device__ __forceinline__ void st_tab4(unsigned int* p, uint4 v,
                                        unsigned long long pol) {
    asm volatile("st.global.L2::cache_hint.v4.u32 [%0], {%1,%2,%3,%4}, %5;"
                 :: "l"(p), "r"(v.x), "r"(v.y), "r"(v.z), "r"(v.w), "l"(pol)
                 : "memory");
}

__device__ __forceinline__ unsigned int ld_tab(const unsigned int* p,
                                               unsigned long long pol) {
    unsigned int v;
    asm("ld.global.nc.L2::cache_hint.u32 %0, [%1], %2;"
        : "=r"(v) : "l"(p), "l"(pol));
    return v;
}

// compute one pair from two already-gathered table words
__device__ __forceinline__ void pair_math(unsigned int A, unsigned int B,
                                          float& lsum, float& wsum) {
    int yA = (int)(A >> (S_BITS + W_BITS));
    int yB = (int)(B >> (S_BITS + W_BITS));
    int dy = yA - yB;
    float sA = (float)((A >> W_BITS) & 0x1FFFFu) * S_INV;
    float sB = (float)((B >> W_BITS) & 0x1FFFFu) * S_INV;
    float wA = (float)(A & 0xFFFu) * W_INV;
    float wB = (float)(B & 0xFFFu) * W_INV;
    float sgn = (dy > 0) ? 1.0f : -1.0f;        // value irrelevant when dy==0
    float x   = -sgn * (sA - sB);               // MARGIN = 0
    float sp  = fmaxf(x, 0.0f) + log1pf(__expf(-fabsf(x)));
    float w   = (dy != 0) ? 0.5f * (wA + wB) : 0.0f;
    lsum = fmaf(sp * fabsf((float)dy), w, lsum);
    wsum += w;
}

__global__ void __launch_bounds__(TPB, BPSM)
k_fused(const float* __restrict__ inputs,
        const int*   __restrict__ targets,
        const float* __restrict__ weight,
        const int*   __restrict__ pair_i,
        const int*   __restrict__ pair_j,
        int n, int np, float* __restrict__ out) {
    int gtid   = blockIdx.x * blockDim.x + threadIdx.x;
    int stride = gridDim.x * blockDim.x;
    unsigned long long pol = evict_last_policy();

    // ================= Phase 1: pack table =================
    int n4 = n >> 2;
    const float4* in4 = (const float4*)inputs;
    for (int t = gtid; t < n4; t += stride) {
        float4 a = __ldcs(in4 + 5 * (size_t)t + 0);
        float4 b = __ldcs(in4 + 5 * (size_t)t + 1);
        float4 c = __ldcs(in4 + 5 * (size_t)t + 2);
        float4 d = __ldcs(in4 + 5 * (size_t)t + 3);
        float4 e = __ldcs(in4 + 5 * (size_t)t + 4);
        int4   y = __ldcs((const int4*)targets + t);
        float4 w = __ldcs((const float4*)weight + t);
        float s0 = score5(a.x, a.y, a.z, a.w, b.x);
        float s1 = score5(b.y, b.z, b.w, c.x, c.y);
        float s2 = score5(c.z, c.w, d.x, d.y, d.z);
        float s3 = score5(d.w, e.x, e.y, e.z, e.w);
        uint4 o;
        o.x = pack_row(s0, y.x, w.x);
        o.y = pack_row(s1, y.y, w.y);
        o.z = pack_row(s2, y.z, w.z);
        o.w = pack_row(s3, y.w, w.w);
        st_tab4(g_tab + 4 * (size_t)t, o, pol);
    }
    int rem = n & 3;
    if (gtid < rem) {
        int i = (n4 << 2) + gtid;
        const float* r = inputs + (size_t)i * 5;
        float s = score5(__ldcs(r + 0), __ldcs(r + 1), __ldcs(r + 2),
                         __ldcs(r + 3), __ldcs(r + 4));
        g_tab[i] = pack_row(s, __ldcs(targets + i), __ldcs(weight + i));
    }

    // ================= Grid barrier (all blocks resident) =================
    __threadfence();
    __syncthreads();
    if (threadIdx.x == 0) {
        atomicAdd(&g_bar, 1u);
        volatile unsigned int* bar = &g_bar;
        while (*bar < gridDim.x) { __nanosleep(64); }
    }
    __syncthreads();
    __threadfence();

    // ================= Phase 2: pairs (software-pipelined) =================
    float lsum = 0.0f, wsum = 0.0f;
    int np4 = np >> 2;
    const int4* pi4 = (const int4*)pair_i;
    const int4* pj4 = (const int4*)pair_j;

    int p = gtid;
    int4 ia, ib;
    if (p < np4) {
        ia = __ldcs(pi4 + p);
        ib = __ldcs(pj4 + p);
    }
    while (p < np4) {
        // issue all 8 gathers for the current group (front-batched)
        unsigned int A0 = ld_tab(g_tab + ia.x, pol);
        unsigned int A1 = ld_tab(g_tab + ia.y, pol);
        unsigned int A2 = ld_tab(g_tab + ia.z, pol);
        unsigned int A3 = ld_tab(g_tab + ia.w, pol);
        unsigned int B0 = ld_tab(g_tab + ib.x, pol);
        unsigned int B1 = ld_tab(g_tab + ib.y, pol);
        unsigned int B2 = ld_tab(g_tab + ib.z, pol);
        unsigned int B3 = ld_tab(g_tab + ib.w, pol);
        // prefetch next iteration's indices while gathers are in flight
        int pn = p + stride;
        if (pn < np4) {
            ia = __ldcs(pi4 + pn);
            ib = __ldcs(pj4 + pn);
        }
        pair_math(A0, B0, lsum, wsum);
        pair_math(A1, B1, lsum, wsum);
        pair_math(A2, B2, lsum, wsum);
        pair_math(A3, B3, lsum, wsum);
        p = pn;
    }
    if (gtid < (np & 3)) {
        int idx = (np4 << 2) + gtid;
        unsigned int A = ld_tab(g_tab + __ldg(pair_i + idx), pol);
        unsigned int B = ld_tab(g_tab + __ldg(pair_j + idx), pol);
        pair_math(A, B, lsum, wsum);
    }

    // ---- block reduction ----
    #pragma unroll
    for (int o = 16; o > 0; o >>= 1) {
        lsum += __shfl_down_sync(0xffffffffu, lsum, o);
        wsum += __shfl_down_sync(0xffffffffu, wsum, o);
    }
    __shared__ float s_l[TPB / 32];
    __shared__ float s_w[TPB / 32];
    int lane = threadIdx.x & 31;
    int wid  = threadIdx.x >> 5;
    if (lane == 0) { s_l[wid] = lsum; s_w[wid] = wsum; }
    __syncthreads();
    if (wid == 0) {
        int nw = blockDim.x >> 5;
        lsum = (lane < nw) ? s_l[lane] : 0.0f;
        wsum = (lane < nw) ? s_w[lane] : 0.0f;
        #pragma unroll
        for (int o = 4; o > 0; o >>= 1) {
            lsum += __shfl_down_sync(0xffffffffu, lsum, o);
            wsum += __shfl_down_sync(0xffffffffu, wsum, o);
        }
        if (lane == 0) g_part[blockIdx.x] = make_float2(lsum, wsum);
    }

    // ---- last block: fold partials, write out, reset counters ----
    __threadfence();
    __shared__ bool is_last;
    if (threadIdx.x == 0) {
        unsigned int old = atomicAdd(&g_count, 1u);
        is_last = (old == gridDim.x - 1);
    }
    __syncthreads();
    if (is_last) {
        double l = 0.0, w = 0.0;
        for (int i = threadIdx.x; i < GRID; i += blockDim.x) {
            float2 pr = g_part[i];
            l += (double)pr.x;
            w += (double)pr.y;
        }
        #pragma unroll
        for (int o = 16; o > 0; o >>= 1) {
            l += __shfl_down_sync(0xffffffffu, l, o);
            w += __shfl_down_sync(0xffffffffu, w, o);
        }
        __shared__ double d_l[TPB / 32];
        __shared__ double d_w[TPB / 32];
        if (lane == 0) { d_l[wid] = l; d_w[wid] = w; }
        __syncthreads();
        if (wid == 0) {
            int nw = blockDim.x >> 5;
            l = (lane < nw) ? d_l[lane] : 0.0;
            w = (lane < nw) ? d_w[lane] : 0.0;
            #pragma unroll
            for (int o = 4; o > 0; o >>= 1) {
                l += __shfl_down_sync(0xffffffffu, l, o);
                w += __shfl_down_sync(0xffffffffu, w, o);
            }
            if (lane == 0) {
                out[0]  = (float)(l / (w + 1e-8));
                g_count = 0;     // reset for next graph replay
                g_bar   = 0;
            }
        }
    }
}

extern "C" void kernel_launch(void* const* d_in, const int* in_sizes, int n_in,
                              void* d_out, int out_size) {
    // metadata order: inputs, targets, cluster_ids, sample_weight, pair_i, pair_j
    const float* inputs  = (const float*)d_in[0];
    const int*   targets = (const int*)  d_in[1];
    const float* weight  = (const float*)d_in[3];
    const int*   pair_i  = (const int*)  d_in[4];
    const int*   pair_j  = (const int*)  d_in[5];

    int n  = in_sizes[1];
    int np = in_sizes[4];

    k_fused<<<GRID, TPB>>>(inputs, targets, weight, pair_i, pair_j,
                           n, np, (float*)d_out);
}